// round 6
// baseline (speedup 1.0000x reference)
#include <cuda_runtime.h>
#include <cuda_bf16.h>
#include <cstdint>

#define BNUM   4
#define SEQ    512
#define DMODEL 1024
#define HDIM   256
#define MTOT   2048
#define KP1    3072      // 3 * DMODEL (hi|lo|hi concat)
#define KP2    768       // 3 * HDIM
#define NJC    1024      // SEQ * 2 (j,c interleaved)
#define NSPLIT 4         // split-K factor for stage-1 GEMM
#define KSPL   (KP1 / NSPLIT)   // 768

// Scratch (allocation-free __device__ globals)
__device__ __align__(16) float         g_p1[NSPLIT * MTOT * HDIM];  // 8 MB partials
__device__ __align__(16) __nv_bfloat16 g_Xp[MTOT * KP1];            // 12 MB
__device__ __align__(16) __nv_bfloat16 g_W1p[HDIM * KP1];           // 1.5 MB
__device__ __align__(16) __nv_bfloat16 g_Ap[MTOT * KP2];            // 3 MB
__device__ __align__(16) __nv_bfloat16 g_Bp[BNUM * NJC * KP2];      // 6 MB

// ---------------------------------------------------------------------------
// helpers
// ---------------------------------------------------------------------------
static __device__ __forceinline__ uint32_t smem_u32(const void* p) {
    uint32_t a;
    asm("{ .reg .u64 t; cvta.to.shared.u64 t, %1; cvt.u32.u64 %0, t; }"
        : "=r"(a) : "l"(p));
    return a;
}
static __device__ __forceinline__ void cp_async16(uint32_t saddr, const void* gaddr) {
    asm volatile("cp.async.cg.shared.global [%0], [%1], 16;"
                 :: "r"(saddr), "l"(gaddr) : "memory");
}
static __device__ __forceinline__ void cp_commit() {
    asm volatile("cp.async.commit_group;" ::: "memory");
}
static __device__ __forceinline__ void cp_wait1() {
    asm volatile("cp.async.wait_group 1;" ::: "memory");
}
static __device__ __forceinline__ void ldsm_x4(uint32_t* r, uint32_t addr) {
    asm volatile("ldmatrix.sync.aligned.m8n8.x4.shared.b16 {%0,%1,%2,%3}, [%4];"
                 : "=r"(r[0]), "=r"(r[1]), "=r"(r[2]), "=r"(r[3]) : "r"(addr));
}
static __device__ __forceinline__ void mma16816(float* d, const uint32_t* a,
                                                uint32_t b0, uint32_t b1) {
    asm volatile(
        "mma.sync.aligned.m16n8k16.row.col.f32.bf16.bf16.f32 "
        "{%0,%1,%2,%3}, {%4,%5,%6,%7}, {%8,%9}, {%0,%1,%2,%3};"
        : "+f"(d[0]), "+f"(d[1]), "+f"(d[2]), "+f"(d[3])
        : "r"(a[0]), "r"(a[1]), "r"(a[2]), "r"(a[3]), "r"(b0), "r"(b1));
}
static __device__ __forceinline__ void st_bf2(__nv_bfloat16* p, __nv_bfloat16 a, __nv_bfloat16 b) {
    __nv_bfloat162 t; t.x = a; t.y = b;
    *(__nv_bfloat162*)p = t;
}
static __device__ __forceinline__ void split1(float v, __nv_bfloat16& h, __nv_bfloat16& l) {
    h = __float2bfloat16_rn(v);
    l = __float2bfloat16_rn(v - __bfloat162float(h));
}

// ---------------------------------------------------------------------------
// Prep 1: split X -> [hi|lo|hi], W1 -> [hi|hi|lo]
// ---------------------------------------------------------------------------
__global__ __launch_bounds__(256) void split_xw(const float* __restrict__ X,
                                                const float* __restrict__ W1) {
    const int NX4 = MTOT * DMODEL / 4;   // 524288
    int idx = blockIdx.x * 256 + threadIdx.x;
    if (idx < NX4) {
        int r = idx >> 8;
        int k = (idx & 255) * 4;
        float4 v = *(const float4*)(X + (size_t)r * DMODEL + k);
        __nv_bfloat16 h0,h1,h2,h3,l0,l1,l2,l3;
        split1(v.x,h0,l0); split1(v.y,h1,l1); split1(v.z,h2,l2); split1(v.w,h3,l3);
        __nv_bfloat16* base = g_Xp + (size_t)r * KP1 + k;
        st_bf2(base,              h0,h1); st_bf2(base+2,              h2,h3);
        st_bf2(base+DMODEL,       l0,l1); st_bf2(base+DMODEL+2,       l2,l3);
        st_bf2(base+2*DMODEL,     h0,h1); st_bf2(base+2*DMODEL+2,     h2,h3);
    } else {
        int i2 = idx - NX4;
        if (i2 >= HDIM * DMODEL / 4) return;
        int r = i2 >> 8;
        int k = (i2 & 255) * 4;
        float4 v = *(const float4*)(W1 + (size_t)r * DMODEL + k);
        __nv_bfloat16 h0,h1,h2,h3,l0,l1,l2,l3;
        split1(v.x,h0,l0); split1(v.y,h1,l1); split1(v.z,h2,l2); split1(v.w,h3,l3);
        __nv_bfloat16* base = g_W1p + (size_t)r * KP1 + k;
        st_bf2(base,              h0,h1); st_bf2(base+2,              h2,h3);
        st_bf2(base+DMODEL,       h0,h1); st_bf2(base+DMODEL+2,       h2,h3);
        st_bf2(base+2*DMODEL,     l0,l1); st_bf2(base+2*DMODEL+2,     l2,l3);
    }
}

// ---------------------------------------------------------------------------
// Prep 2 (fused reduce): o = sum_s p1[s] + b1; A' = [o_hi|o_lo|o_hi];
// B' rows jc=2j+c: v=o*w_c, [v_hi|v_hi|v_lo]
// ---------------------------------------------------------------------------
__global__ __launch_bounds__(256) void prep_o(const float* __restrict__ W2,
                                              const float* __restrict__ b1) {
    int idx = blockIdx.x * 256 + threadIdx.x;       // over 2048*64
    int m = idx >> 6;
    int h = (idx & 63) * 4;

    float4 o4 = *(const float4*)(g_p1 + (size_t)m * HDIM + h);
#pragma unroll
    for (int s = 1; s < NSPLIT; ++s) {
        float4 p = *(const float4*)(g_p1 + ((size_t)s * MTOT + m) * HDIM + h);
        o4.x += p.x; o4.y += p.y; o4.z += p.z; o4.w += p.w;
    }
    float4 bb = *(const float4*)(b1 + h);
    o4.x += bb.x; o4.y += bb.y; o4.z += bb.z; o4.w += bb.w;

    __nv_bfloat16 h0,h1,h2,h3,l0,l1,l2,l3;
    split1(o4.x,h0,l0); split1(o4.y,h1,l1); split1(o4.z,h2,l2); split1(o4.w,h3,l3);
    __nv_bfloat16* abase = g_Ap + (size_t)m * KP2 + h;
    st_bf2(abase,          h0,h1); st_bf2(abase+2,          h2,h3);
    st_bf2(abase+HDIM,     l0,l1); st_bf2(abase+HDIM+2,     l2,l3);
    st_bf2(abase+2*HDIM,   h0,h1); st_bf2(abase+2*HDIM+2,   h2,h3);

    int b = m >> 9, j = m & 511;
    float4 w0 = *(const float4*)(W2 + h);
    float4 w1 = *(const float4*)(W2 + HDIM + h);
#pragma unroll
    for (int c = 0; c < 2; ++c) {
        float4 w = c ? w1 : w0;
        float4 v;
        v.x = o4.x * w.x; v.y = o4.y * w.y; v.z = o4.z * w.z; v.w = o4.w * w.w;
        __nv_bfloat16 vh0,vh1,vh2,vh3,vl0,vl1,vl2,vl3;
        split1(v.x,vh0,vl0); split1(v.y,vh1,vl1); split1(v.z,vh2,vl2); split1(v.w,vh3,vl3);
        __nv_bfloat16* bbase = g_Bp + ((size_t)b * NJC + 2 * j + c) * KP2 + h;
        st_bf2(bbase,          vh0,vh1); st_bf2(bbase+2,          vh2,vh3);
        st_bf2(bbase+HDIM,     vh0,vh1); st_bf2(bbase+HDIM+2,     vh2,vh3);
        st_bf2(bbase+2*HDIM,   vl0,vl1); st_bf2(bbase+2*HDIM+2,   vl2,vl3);
    }
}

// ---------------------------------------------------------------------------
// mma.sync bf16 TN GEMM: CTA tile 128x128, BK=32, 3-stage cp.async pipeline,
// 256 threads / 8 warps (2M x 4N), warp tile 64x32.
// smem tile rows are 64B (32 bf16); XOR swizzle: chunk ^= (row>>1)&3.
// mode 0: C = g_p1[z]          (A = g_Xp, B = g_W1p, k-window z*768..)
// mode 1: C = out + b2[col&1]  (A = g_Ap, B = g_Bp)
// ---------------------------------------------------------------------------
#define BM   128
#define BN   128
#define BK   32
#define STB  16384                    // stage bytes: A 8KB + B 8KB
#define SMEM_SZ (3 * STB)             // 49152 == default 48KB limit
#define NC   24                       // 768 / 32 for both gemms

__global__ __launch_bounds__(256) void gemm_kernel(int mode,
                                                   const float* __restrict__ bias,
                                                   float* __restrict__ outp) {
    extern __shared__ char smem[];
    const uint32_t sbase = smem_u32(smem);
    const int tid = threadIdx.x;
    const int wid = tid >> 5, lane = tid & 31;
    const int wm = wid & 1;                          // M warp (2)
    const int wn = wid >> 1;                         // N warp (4)
    const int m0 = blockIdx.y * BM, n0 = blockIdx.x * BN, bz = blockIdx.z;

    const __nv_bfloat16* Ab;
    const __nv_bfloat16* Bb;
    int Kp;
    if (mode == 0) { Ab = g_Xp + (size_t)m0 * KP1 + bz * KSPL;
                     Bb = g_W1p + (size_t)n0 * KP1 + bz * KSPL; Kp = KP1; }
    else           { Ab = g_Ap + ((size_t)(bz * SEQ + m0)) * KP2;
                     Bb = g_Bp + ((size_t)(bz * NJC + n0)) * KP2; Kp = KP2; }

    // cp.async mapping: 256 thr; row = tid>>1 (0..127), chunks (tid&1)*2 + {0,1}
    const int lrow = tid >> 1;
    const int lc0  = (tid & 1) * 2;
    const int lxr  = (lrow >> 1) & 3;
    const uint32_t sw0 = (uint32_t)(((lc0 + 0) ^ lxr) << 4);
    const uint32_t sw1 = (uint32_t)(((lc0 + 1) ^ lxr) << 4);

    float acc[4][4][4];
#pragma unroll
    for (int mi = 0; mi < 4; ++mi)
#pragma unroll
        for (int j = 0; j < 4; ++j)
#pragma unroll
            for (int e = 0; e < 4; ++e) acc[mi][j][e] = 0.0f;

    // prologue: stages 0,1
#pragma unroll
    for (int s = 0; s < 2; ++s) {
        const __nv_bfloat16* Ag = Ab + s * BK + (size_t)lrow * Kp + lc0 * 8;
        const __nv_bfloat16* Bg = Bb + s * BK + (size_t)lrow * Kp + lc0 * 8;
        const uint32_t rowA = sbase + s * STB + lrow * 64;
        const uint32_t rowB = rowA + 8192;
        cp_async16(rowA + sw0, Ag);
        cp_async16(rowA + sw1, Ag + 8);
        cp_async16(rowB + sw0, Bg);
        cp_async16(rowB + sw1, Bg + 8);
        cp_commit();
    }

    // ldmatrix bases: rows +16 share the same xor key ((+16)>>1 = +8, &3 same)
    const int arow = wm * 64 + (lane & 15);
    const int brow = wn * 32 + (lane & 15);
    const int kl   = lane >> 4;                      // 16B half within k16
    const int axr  = (arow >> 1) & 3;
    const int bxr  = (brow >> 1) & 3;
    const uint32_t aRow = sbase + (uint32_t)(arow * 64);
    const uint32_t bRow = sbase + 8192 + (uint32_t)(brow * 64);

    for (int kc = 0; kc < NC; ++kc) {
        cp_wait1();
        __syncthreads();

        const int s = kc % 3;
        const uint32_t aS = aRow + (uint32_t)(s * STB);
        const uint32_t bS = bRow + (uint32_t)(s * STB);
#pragma unroll
        for (int s2 = 0; s2 < 2; ++s2) {             // two k16 per k32 stage
            const int c16 = s2 * 2 + kl;
            const uint32_t swa = (uint32_t)((c16 ^ axr) << 4);
            const uint32_t swb = (uint32_t)((c16 ^ bxr) << 4);
            uint32_t am[4][4], bn[2][4];
#pragma unroll
            for (int mi = 0; mi < 4; ++mi)
                ldsm_x4(am[mi], aS + mi * 1024 + swa);
#pragma unroll
            for (int ni = 0; ni < 2; ++ni)
                ldsm_x4(bn[ni], bS + ni * 1024 + swb);
#pragma unroll
            for (int mi = 0; mi < 4; ++mi) {
#pragma unroll
                for (int ni = 0; ni < 2; ++ni) {
                    mma16816(acc[mi][ni * 2 + 0], am[mi], bn[ni][0], bn[ni][2]);
                    mma16816(acc[mi][ni * 2 + 1], am[mi], bn[ni][1], bn[ni][3]);
                }
            }
        }

        if (kc + 2 < NC) {
            const int s2 = (kc + 2) % 3;
            const __nv_bfloat16* Ag = Ab + (kc + 2) * BK + (size_t)lrow * Kp + lc0 * 8;
            const __nv_bfloat16* Bg = Bb + (kc + 2) * BK + (size_t)lrow * Kp + lc0 * 8;
            const uint32_t rowA = sbase + s2 * STB + lrow * 64;
            const uint32_t rowB = rowA + 8192;
            cp_async16(rowA + sw0, Ag);
            cp_async16(rowA + sw1, Ag + 8);
            cp_async16(rowB + sw0, Bg);
            cp_async16(rowB + sw1, Bg + 8);
        }
        cp_commit();
    }

    // epilogue
    const int rbase = m0 + wm * 64 + (lane >> 2);
    const int cbase = n0 + wn * 32 + (lane & 3) * 2;
    float bv0 = 0.f, bv1 = 0.f;
    if (mode == 1) { bv0 = bias[0]; bv1 = bias[1]; }
#pragma unroll
    for (int mi = 0; mi < 4; ++mi) {
        const int r0 = rbase + mi * 16;
#pragma unroll
        for (int j = 0; j < 4; ++j) {
            const int col = cbase + j * 8;
            if (mode == 0) {
                float* base = g_p1 + (size_t)bz * MTOT * HDIM;
                float2 v0; v0.x = acc[mi][j][0]; v0.y = acc[mi][j][1];
                float2 v1; v1.x = acc[mi][j][2]; v1.y = acc[mi][j][3];
                *(float2*)(base + (size_t)r0 * HDIM + col)       = v0;
                *(float2*)(base + (size_t)(r0 + 8) * HDIM + col) = v1;
            } else {
                float2 v0; v0.x = acc[mi][j][0] + bv0; v0.y = acc[mi][j][1] + bv1;
                float2 v1; v1.x = acc[mi][j][2] + bv0; v1.y = acc[mi][j][3] + bv1;
                float* base = outp + ((size_t)bz * SEQ) * NJC;
                *(float2*)(base + (size_t)r0 * NJC + col)       = v0;
                *(float2*)(base + (size_t)(r0 + 8) * NJC + col) = v1;
            }
        }
    }
}

// ---------------------------------------------------------------------------
extern "C" void kernel_launch(void* const* d_in, const int* in_sizes, int n_in,
                              void* d_out, int out_size)
{
    const float* x  = (const float*)d_in[0];   // [4, 512, 1024]
    const float* W1 = (const float*)d_in[1];   // [256, 1024]
    const float* b1 = (const float*)d_in[2];   // [256]
    const float* W2 = (const float*)d_in[3];   // [2, 256]
    const float* b2 = (const float*)d_in[4];   // [2]
    float* out = (float*)d_out;                // [4, 512, 512, 2]

    // Prep 1: split inputs
    split_xw<<<2304, 256>>>(x, W1);

    // Stage 1 GEMM (split-K=4): p1[z] = x @ W1^T over k-window z
    gemm_kernel<<<dim3(HDIM / BN, MTOT / BM, NSPLIT), 256, SMEM_SZ>>>(0, nullptr, nullptr);

    // Prep 2: fused reduce(+b1) + split + fold W2 into B operand
    prep_o<<<512, 256>>>(W2, b1);

    // Stage 2 GEMM: out[b,i,jc] = A @ B'^T + b2  (M=512, N=1024, K'=768) x4
    gemm_kernel<<<dim3(NJC / BN, SEQ / BM, BNUM), 256, SMEM_SZ>>>(1, b2, out);
}

// round 7
// speedup vs baseline: 1.1016x; 1.1016x over previous
#include <cuda_runtime.h>
#include <cuda_bf16.h>
#include <cstdint>

#define BNUM   4
#define SEQ    512
#define DMODEL 1024
#define HDIM   256
#define MTOT   2048
#define KP1    3072      // 3 * DMODEL (hi|lo|hi concat)
#define KP2    768       // 3 * HDIM
#define NJC    1024      // SEQ * 2 (j,c interleaved)
#define NSPLIT 4         // split-K factor for stage-1 GEMM
#define KSPL   (KP1 / NSPLIT)   // 768

// Scratch (allocation-free __device__ globals)
__device__ __align__(16) float         g_p1[NSPLIT * MTOT * HDIM];  // 8 MB partials
__device__ __align__(16) __nv_bfloat16 g_Xp[MTOT * KP1];            // 12 MB
__device__ __align__(16) __nv_bfloat16 g_W1p[HDIM * KP1];           // 1.5 MB
__device__ __align__(16) __nv_bfloat16 g_Ap[MTOT * KP2];            // 3 MB
__device__ __align__(16) __nv_bfloat16 g_Bp[BNUM * NJC * KP2];      // 6 MB

// ---------------------------------------------------------------------------
// helpers
// ---------------------------------------------------------------------------
static __device__ __forceinline__ uint32_t smem_u32(const void* p) {
    uint32_t a;
    asm("{ .reg .u64 t; cvta.to.shared.u64 t, %1; cvt.u32.u64 %0, t; }"
        : "=r"(a) : "l"(p));
    return a;
}
static __device__ __forceinline__ void cp_async16(uint32_t saddr, const void* gaddr) {
    asm volatile("cp.async.cg.shared.global [%0], [%1], 16;"
                 :: "r"(saddr), "l"(gaddr) : "memory");
}
static __device__ __forceinline__ void cp_commit() {
    asm volatile("cp.async.commit_group;" ::: "memory");
}
static __device__ __forceinline__ void cp_wait2() {
    asm volatile("cp.async.wait_group 2;" ::: "memory");
}
static __device__ __forceinline__ void cp_wait0() {
    asm volatile("cp.async.wait_group 0;" ::: "memory");
}
static __device__ __forceinline__ void ldsm_x4(uint32_t* r, uint32_t addr) {
    asm volatile("ldmatrix.sync.aligned.m8n8.x4.shared.b16 {%0,%1,%2,%3}, [%4];"
                 : "=r"(r[0]), "=r"(r[1]), "=r"(r[2]), "=r"(r[3]) : "r"(addr));
}
static __device__ __forceinline__ void mma16816(float* d, const uint32_t* a,
                                                uint32_t b0, uint32_t b1) {
    asm volatile(
        "mma.sync.aligned.m16n8k16.row.col.f32.bf16.bf16.f32 "
        "{%0,%1,%2,%3}, {%4,%5,%6,%7}, {%8,%9}, {%0,%1,%2,%3};"
        : "+f"(d[0]), "+f"(d[1]), "+f"(d[2]), "+f"(d[3])
        : "r"(a[0]), "r"(a[1]), "r"(a[2]), "r"(a[3]), "r"(b0), "r"(b1));
}
static __device__ __forceinline__ void st_bf2(__nv_bfloat16* p, __nv_bfloat16 a, __nv_bfloat16 b) {
    __nv_bfloat162 t; t.x = a; t.y = b;
    *(__nv_bfloat162*)p = t;
}
static __device__ __forceinline__ void split1(float v, __nv_bfloat16& h, __nv_bfloat16& l) {
    h = __float2bfloat16_rn(v);
    l = __float2bfloat16_rn(v - __bfloat162float(h));
}

// ---------------------------------------------------------------------------
// Prep 1: split X -> [hi|lo|hi], W1 -> [hi|hi|lo]
// ---------------------------------------------------------------------------
__global__ __launch_bounds__(256) void split_xw(const float* __restrict__ X,
                                                const float* __restrict__ W1) {
    const int NX4 = MTOT * DMODEL / 4;   // 524288
    int idx = blockIdx.x * 256 + threadIdx.x;
    if (idx < NX4) {
        int r = idx >> 8;
        int k = (idx & 255) * 4;
        float4 v = *(const float4*)(X + (size_t)r * DMODEL + k);
        __nv_bfloat16 h0,h1,h2,h3,l0,l1,l2,l3;
        split1(v.x,h0,l0); split1(v.y,h1,l1); split1(v.z,h2,l2); split1(v.w,h3,l3);
        __nv_bfloat16* base = g_Xp + (size_t)r * KP1 + k;
        st_bf2(base,              h0,h1); st_bf2(base+2,              h2,h3);
        st_bf2(base+DMODEL,       l0,l1); st_bf2(base+DMODEL+2,       l2,l3);
        st_bf2(base+2*DMODEL,     h0,h1); st_bf2(base+2*DMODEL+2,     h2,h3);
    } else {
        int i2 = idx - NX4;
        if (i2 >= HDIM * DMODEL / 4) return;
        int r = i2 >> 8;
        int k = (i2 & 255) * 4;
        float4 v = *(const float4*)(W1 + (size_t)r * DMODEL + k);
        __nv_bfloat16 h0,h1,h2,h3,l0,l1,l2,l3;
        split1(v.x,h0,l0); split1(v.y,h1,l1); split1(v.z,h2,l2); split1(v.w,h3,l3);
        __nv_bfloat16* base = g_W1p + (size_t)r * KP1 + k;
        st_bf2(base,              h0,h1); st_bf2(base+2,              h2,h3);
        st_bf2(base+DMODEL,       h0,h1); st_bf2(base+DMODEL+2,       h2,h3);
        st_bf2(base+2*DMODEL,     l0,l1); st_bf2(base+2*DMODEL+2,     l2,l3);
    }
}

// ---------------------------------------------------------------------------
// Prep 2 (fused reduce): o = sum_s p1[s] + b1; A' = [o_hi|o_lo|o_hi];
// B' rows jc=2j+c: v=o*w_c, [v_hi|v_hi|v_lo]
// ---------------------------------------------------------------------------
__global__ __launch_bounds__(256) void prep_o(const float* __restrict__ W2,
                                              const float* __restrict__ b1) {
    int idx = blockIdx.x * 256 + threadIdx.x;       // over 2048*64
    int m = idx >> 6;
    int h = (idx & 63) * 4;

    float4 o4 = *(const float4*)(g_p1 + (size_t)m * HDIM + h);
#pragma unroll
    for (int s = 1; s < NSPLIT; ++s) {
        float4 p = *(const float4*)(g_p1 + ((size_t)s * MTOT + m) * HDIM + h);
        o4.x += p.x; o4.y += p.y; o4.z += p.z; o4.w += p.w;
    }
    float4 bb = *(const float4*)(b1 + h);
    o4.x += bb.x; o4.y += bb.y; o4.z += bb.z; o4.w += bb.w;

    __nv_bfloat16 h0,h1,h2,h3,l0,l1,l2,l3;
    split1(o4.x,h0,l0); split1(o4.y,h1,l1); split1(o4.z,h2,l2); split1(o4.w,h3,l3);
    __nv_bfloat16* abase = g_Ap + (size_t)m * KP2 + h;
    st_bf2(abase,          h0,h1); st_bf2(abase+2,          h2,h3);
    st_bf2(abase+HDIM,     l0,l1); st_bf2(abase+HDIM+2,     l2,l3);
    st_bf2(abase+2*HDIM,   h0,h1); st_bf2(abase+2*HDIM+2,   h2,h3);

    int b = m >> 9, j = m & 511;
    float4 w0 = *(const float4*)(W2 + h);
    float4 w1 = *(const float4*)(W2 + HDIM + h);
#pragma unroll
    for (int c = 0; c < 2; ++c) {
        float4 w = c ? w1 : w0;
        float4 v;
        v.x = o4.x * w.x; v.y = o4.y * w.y; v.z = o4.z * w.z; v.w = o4.w * w.w;
        __nv_bfloat16 vh0,vh1,vh2,vh3,vl0,vl1,vl2,vl3;
        split1(v.x,vh0,vl0); split1(v.y,vh1,vl1); split1(v.z,vh2,vl2); split1(v.w,vh3,vl3);
        __nv_bfloat16* bbase = g_Bp + ((size_t)b * NJC + 2 * j + c) * KP2 + h;
        st_bf2(bbase,          vh0,vh1); st_bf2(bbase+2,          vh2,vh3);
        st_bf2(bbase+HDIM,     vh0,vh1); st_bf2(bbase+HDIM+2,     vh2,vh3);
        st_bf2(bbase+2*HDIM,   vl0,vl1); st_bf2(bbase+2*HDIM+2,   vl2,vl3);
    }
}

// ---------------------------------------------------------------------------
// mma.sync bf16 TN GEMM: D[64,64] = A[64,K] * B[64,K]^T, BK=32, 4-stage
// cp.async pipeline, 256 threads / 8 warps. Warps 0-3 consume k16 #0 of each
// stage, warps 4-7 consume k16 #1 (in-CTA K-split); combined via smem.
// Stage block (8KB): A tile 64x64B at +0, B tile 64x64B at +4096.
// XOR swizzle: 16B chunk ^= (row>>1)&3.
// mode 0: C = g_p1[z]          (A = g_Xp, B = g_W1p, k-window z*768..)
// mode 1: C = out + b2[col&1]  (A = g_Ap, B = g_Bp)
// ---------------------------------------------------------------------------
#define BM   64
#define BN   64
#define BK   32
#define STB  8192                     // stage bytes: A 4KB + B 4KB
#define NSTG 4
#define SMEM_SZ (NSTG * STB)          // 32768
#define NC   24                       // 768 / 32 for both gemms

__global__ __launch_bounds__(256, 4) void gemm_kernel(int mode,
                                                      const float* __restrict__ bias,
                                                      float* __restrict__ outp) {
    extern __shared__ char smem[];
    const uint32_t sbase = smem_u32(smem);
    const int tid = threadIdx.x;
    const int wid = tid >> 5, lane = tid & 31;
    const int grp = wid >> 2;                        // k16 group 0/1
    const int wm = wid & 1, wn = (wid >> 1) & 1;     // 2x2 warp grid per group
    const int m0 = blockIdx.y * BM, n0 = blockIdx.x * BN, bz = blockIdx.z;

    const __nv_bfloat16* Ab;
    const __nv_bfloat16* Bb;
    int Kp;
    if (mode == 0) { Ab = g_Xp + (size_t)m0 * KP1 + bz * KSPL;
                     Bb = g_W1p + (size_t)n0 * KP1 + bz * KSPL; Kp = KP1; }
    else           { Ab = g_Ap + ((size_t)(bz * SEQ + m0)) * KP2;
                     Bb = g_Bp + ((size_t)(bz * NJC + n0)) * KP2; Kp = KP2; }

    // cp.async mapping: row = tid>>2 (0..63), chunk = tid&3; one 16B per operand
    const int lrow = tid >> 2;
    const int lc   = tid & 3;
    const uint32_t sw = (uint32_t)((lc ^ ((lrow >> 1) & 3)) << 4);
    const uint32_t rowOff = (uint32_t)(lrow * 64) + sw;

    float acc[2][4][4];
#pragma unroll
    for (int mt = 0; mt < 2; ++mt)
#pragma unroll
        for (int j = 0; j < 4; ++j)
#pragma unroll
            for (int e = 0; e < 4; ++e) acc[mt][j][e] = 0.0f;

    // prologue: stages 0..2
#pragma unroll
    for (int s = 0; s < 3; ++s) {
        const __nv_bfloat16* Ag = Ab + s * BK + (size_t)lrow * Kp + lc * 8;
        const __nv_bfloat16* Bg = Bb + s * BK + (size_t)lrow * Kp + lc * 8;
        cp_async16(sbase + s * STB + rowOff,        Ag);
        cp_async16(sbase + s * STB + 4096 + rowOff, Bg);
        cp_commit();
    }

    // ldmatrix bases; rows +16 share the same xor key
    const int arow = wm * 32 + (lane & 15);
    const int brow = wn * 32 + (lane & 15);
    const int kl   = lane >> 4;                      // 16B half within k16
    const int c16  = grp * 2 + kl;                   // chunk this thread reads
    const int axr  = (arow >> 1) & 3;
    const int bxr  = (brow >> 1) & 3;
    const uint32_t aOff = (uint32_t)(arow * 64) + (uint32_t)((c16 ^ axr) << 4);
    const uint32_t bOff = 4096u + (uint32_t)(brow * 64) + (uint32_t)((c16 ^ bxr) << 4);

    for (int kc = 0; kc < NC; ++kc) {
        cp_wait2();
        __syncthreads();

        const uint32_t stg = sbase + (uint32_t)((kc & 3) * STB);
        uint32_t a0[4], a1[4], b0[4], b1[4];
        ldsm_x4(a0, stg + aOff);
        ldsm_x4(a1, stg + aOff + 16 * 64);
        ldsm_x4(b0, stg + bOff);
        ldsm_x4(b1, stg + bOff + 16 * 64);
        mma16816(acc[0][0], a0, b0[0], b0[2]);
        mma16816(acc[0][1], a0, b0[1], b0[3]);
        mma16816(acc[0][2], a0, b1[0], b1[2]);
        mma16816(acc[0][3], a0, b1[1], b1[3]);
        mma16816(acc[1][0], a1, b0[0], b0[2]);
        mma16816(acc[1][1], a1, b0[1], b0[3]);
        mma16816(acc[1][2], a1, b1[0], b1[2]);
        mma16816(acc[1][3], a1, b1[1], b1[3]);

        __syncthreads();
        if (kc + 3 < NC) {
            const int s2 = (kc + 3) & 3;
            const __nv_bfloat16* Ag = Ab + (kc + 3) * BK + (size_t)lrow * Kp + lc * 8;
            const __nv_bfloat16* Bg = Bb + (kc + 3) * BK + (size_t)lrow * Kp + lc * 8;
            cp_async16(sbase + s2 * STB + rowOff,        Ag);
            cp_async16(sbase + s2 * STB + 4096 + rowOff, Bg);
        }
        cp_commit();
    }

    // ---- combine the two k-groups through smem, then store (group 0) ----
    cp_wait0();
    __syncthreads();

    float* sC = (float*)smem;                        // 64 x 66 fp32 = 16.9KB
    const int rr = lane >> 2;                        // 0..7
    const int cc0 = wn * 32 + (lane & 3) * 2;        // col base

    if (grp == 1) {
#pragma unroll
        for (int mt = 0; mt < 2; ++mt)
#pragma unroll
            for (int j = 0; j < 4; ++j) {
                const int r0 = wm * 32 + rr + mt * 16;
                const int c  = cc0 + j * 8;
                float2 v0; v0.x = acc[mt][j][0]; v0.y = acc[mt][j][1];
                float2 v1; v1.x = acc[mt][j][2]; v1.y = acc[mt][j][3];
                *(float2*)(sC + r0 * 66 + c)       = v0;
                *(float2*)(sC + (r0 + 8) * 66 + c) = v1;
            }
    }
    __syncthreads();

    if (grp == 0) {
        const int row0 = m0 + wm * 32 + rr;
        const int col0 = n0 + cc0;
        float bv0 = 0.f, bv1 = 0.f;
        if (mode == 1) { bv0 = bias[0]; bv1 = bias[1]; }
#pragma unroll
        for (int mt = 0; mt < 2; ++mt) {
#pragma unroll
            for (int j = 0; j < 4; ++j) {
                const int lr0 = wm * 32 + rr + mt * 16;
                const int lc2 = cc0 + j * 8;
                float2 p0 = *(float2*)(sC + lr0 * 66 + lc2);
                float2 p1 = *(float2*)(sC + (lr0 + 8) * 66 + lc2);
                const int col = col0 + j * 8;
                const int r0 = row0 + mt * 16;
                if (mode == 0) {
                    float* base = g_p1 + (size_t)bz * MTOT * HDIM;
                    float2 v0; v0.x = acc[mt][j][0] + p0.x; v0.y = acc[mt][j][1] + p0.y;
                    float2 v1; v1.x = acc[mt][j][2] + p1.x; v1.y = acc[mt][j][3] + p1.y;
                    *(float2*)(base + (size_t)r0 * HDIM + col)       = v0;
                    *(float2*)(base + (size_t)(r0 + 8) * HDIM + col) = v1;
                } else {
                    float2 v0; v0.x = acc[mt][j][0] + p0.x + bv0; v0.y = acc[mt][j][1] + p0.y + bv1;
                    float2 v1; v1.x = acc[mt][j][2] + p1.x + bv0; v1.y = acc[mt][j][3] + p1.y + bv1;
                    float* base = outp + ((size_t)bz * SEQ) * NJC;
                    *(float2*)(base + (size_t)r0 * NJC + col)       = v0;
                    *(float2*)(base + (size_t)(r0 + 8) * NJC + col) = v1;
                }
            }
        }
    }
}

// ---------------------------------------------------------------------------
extern "C" void kernel_launch(void* const* d_in, const int* in_sizes, int n_in,
                              void* d_out, int out_size)
{
    const float* x  = (const float*)d_in[0];   // [4, 512, 1024]
    const float* W1 = (const float*)d_in[1];   // [256, 1024]
    const float* b1 = (const float*)d_in[2];   // [256]
    const float* W2 = (const float*)d_in[3];   // [2, 256]
    const float* b2 = (const float*)d_in[4];   // [2]
    float* out = (float*)d_out;                // [4, 512, 512, 2]

    // Prep 1: split inputs
    split_xw<<<2304, 256>>>(x, W1);

    // Stage 1 GEMM (split-K=4): p1[z] = x @ W1^T over k-window z
    gemm_kernel<<<dim3(HDIM / BN, MTOT / BM, NSPLIT), 256, SMEM_SZ>>>(0, nullptr, nullptr);

    // Prep 2: fused reduce(+b1) + split + fold W2 into B operand
    prep_o<<<512, 256>>>(W2, b1);

    // Stage 2 GEMM: out[b,i,jc] = A @ B'^T + b2  (M=512, N=1024, K'=768) x4
    gemm_kernel<<<dim3(NJC / BN, SEQ / BM, BNUM), 256, SMEM_SZ>>>(1, b2, out);
}